// round 11
// baseline (speedup 1.0000x reference)
#include <cuda_runtime.h>
#include <math.h>
#include <float.h>

// ---------------- problem constants ----------------
#define NNODES 1024
#define NPGC   128
#define NBG    8
#define KNBR   64
#define HDIM   600
#define GDIM   50
#define LAY    6
#define NEDGE  (NNODES*KNBR)   // 65536
#define EA_LD  52              // gaussian features padded 50 -> 52 (16B-aligned rows)

// ---------------- scratch (static device globals; no allocation) ----------------
__device__ float g_A[NEDGE * HDIM];        // ssp(ea@W1+b1), per layer (157 MB)
__device__ float g_eattr[NEDGE * EA_LD];   // gaussian smearing (13.6 MB)
__device__ float g_h[2][NNODES * HDIM];    // node features ping-pong
__device__ float g_x1[NNODES * HDIM];
__device__ float g_msg[NNODES * HDIM];
__device__ float g_t[NNODES * HDIM];
__device__ int   g_nbr[NEDGE];
__device__ float g_C[NEDGE];
__device__ float g_d[NEDGE];
__device__ float g_pooled[NBG * HDIM];

// ---------------- shifted softplus ----------------
// ssp(x) = log(1+e^x) - log 2 = x/2 + log(cosh(x/2))
// |x| < 1 (essentially always with this data): even Taylor poly, err < 3e-6.
// fallback: exact stable formula.
__device__ __forceinline__ float sspf(float x) {
    float u = x * x;
    if (u < 1.0f) {
        float p = fmaf(u, -2.6356299e-5f, 3.4722222e-4f);
        p = fmaf(u, p, -5.2083333e-3f);
        p = fmaf(u, p, 0.125f);
        return fmaf(u, p, 0.5f * x);
    }
    return fmaxf(x, 0.f) + log1pf(expf(-fabsf(x))) - 0.69314718056f;
}

// ---------------- graph build: one warp per node ----------------
// Matches jax: ok = (d2 <= 100) & !self ; top_k(-d2, 64), tie -> lower index.
__global__ void build_graph_kernel(const float* __restrict__ pos,
                                   int* __restrict__ nbr,
                                   float* __restrict__ dbuf,
                                   float* __restrict__ cbuf) {
    __shared__ float spos[NPGC * 3];
    const int t = threadIdx.x;
    const int w = t >> 5, lane = t & 31;
    const int node = blockIdx.x * 8 + w;        // 128 blocks x 8 warps = 1024 nodes
    const int g = node >> 7;                    // all warps in block share graph
    const int i = node & 127;

    for (int idx = t; idx < NPGC * 3; idx += blockDim.x)
        spos[idx] = pos[g * NPGC * 3 + idx];
    __syncthreads();

    const float px = spos[i*3+0], py = spos[i*3+1], pz = spos[i*3+2];
    float d2v[4];
#pragma unroll
    for (int c = 0; c < 4; c++) {
        int j = lane + 32 * c;
        float dx = px - spos[j*3+0];
        float dy = py - spos[j*3+1];
        float dz = pz - spos[j*3+2];
        float d2 = fmaf(dx, dx, fmaf(dy, dy, dz * dz));
        bool ok = (j != i) && (d2 <= 100.0f);
        d2v[c] = ok ? d2 : FLT_MAX;
    }

    const float PIF = 3.14159265358979f;
    for (int slot = 0; slot < KNBR; slot++) {
        // local min (strict < keeps lowest j on ties since j increases with c)
        float mv = d2v[0]; int mc = 0;
#pragma unroll
        for (int c = 1; c < 4; c++) if (d2v[c] < mv) { mv = d2v[c]; mc = c; }
        int mj = lane + 32 * mc;
        // warp reduce with (val, idx) tie-break
#pragma unroll
        for (int off = 16; off > 0; off >>= 1) {
            float ov = __shfl_down_sync(0xFFFFFFFFu, mv, off);
            int   oj = __shfl_down_sync(0xFFFFFFFFu, mj, off);
            if (ov < mv || (ov == mv && oj < mj)) { mv = ov; mj = oj; }
        }
        mv = __shfl_sync(0xFFFFFFFFu, mv, 0);
        mj = __shfl_sync(0xFFFFFFFFu, mj, 0);
        // invalidate chosen candidate
        if (lane == (mj & 31)) d2v[mj >> 5] = FLT_MAX;
        if (lane == 0) {
            int e = node * KNBR + slot;
            if (mv < 1e37f) {
                nbr[e] = g * NPGC + mj;
                float d = sqrtf(mv);
                dbuf[e] = d;
                cbuf[e] = 0.5f * (cosf(d * PIF / 10.0f) + 1.0f);
            } else {
                nbr[e] = node;   // self (safe), zero-weighted
                dbuf[e] = 0.f;
                cbuf[e] = 0.f;
            }
        }
    }
}

// ---------------- gaussian smearing ----------------
__global__ void edge_feat_kernel(const float* __restrict__ dbuf,
                                 float* __restrict__ eattr) {
    int idx = blockIdx.x * blockDim.x + threadIdx.x;
    if (idx >= NEDGE * EA_LD) return;
    int e = idx / EA_LD;
    int c = idx - e * EA_LD;
    float v = 0.f;
    if (c < GDIM) {
        const float step = 10.0f / 49.0f;
        const float coeff = -0.5f / (step * step);
        float t = dbuf[e] - c * step;
        v = __expf(coeff * t * t);
    }
    eattr[idx] = v;
}

// ---------------- embedding gather ----------------
__global__ void embed_kernel(const float* __restrict__ emb,
                             const int* __restrict__ z,
                             float* __restrict__ h) {
    int idx = blockIdx.x * blockDim.x + threadIdx.x;
    if (idx >= NNODES * HDIM) return;
    int n = idx / HDIM, c = idx - n * HDIM;
    h[idx] = emb[z[n] * HDIM + c];
}

// ---------------- generic GEMM: out[M x 600] = X[M x kx] @ W[kw x 600] (+epi) ----------
// BM=128, BN=64, BK=16, 256 threads, 8x4 micro-tile, reg-prefetch.
// EPI: 0 = plain, 1 = ssp(acc + bias), 2 = res + acc + bias
#define BM 128
#define BN 64
#define BK 16

template<int EPI>
__global__ __launch_bounds__(256) void gemm_kernel(
    const float* __restrict__ X, int ldx, int kx, int kw,
    const float* __restrict__ W,
    const float* __restrict__ bias,
    const float* __restrict__ res,
    float* __restrict__ out)
{
    __shared__ float Xs[BK][BM + 4];
    __shared__ float Ws[BK][BN + 4];
    const int t = threadIdx.x;
    const int ty = t >> 4, tx = t & 15;
    const int row0 = blockIdx.x * BM;
    const int h0 = blockIdx.y * BN;

    float acc[8][4];
#pragma unroll
    for (int i = 0; i < 8; i++)
#pragma unroll
        for (int j = 0; j < 4; j++) acc[i][j] = 0.f;

    const int kmax = (kx > kw) ? kx : kw;
    const int nStages = (kmax + BK - 1) / BK;

    const int xkoff = (t & 1) * 8;
    const float* Xrow = X + (size_t)(row0 + (t >> 1)) * ldx;
    const int wk = ty;
    const int wcol = tx * 4;
    const bool wcolOk = (h0 + wcol) < HDIM;

    float4 xr0, xr1, wr;
    const float4 f4z = make_float4(0.f, 0.f, 0.f, 0.f);

    auto loadStage = [&](int k0) {
        int kc = k0 + xkoff;
        xr0 = (kc < kx) ? *(const float4*)(Xrow + kc) : f4z;
        xr1 = (kc + 4 < kx) ? *(const float4*)(Xrow + kc + 4) : f4z;
        int kr = k0 + wk;
        wr = (kr < kw && wcolOk) ? *(const float4*)(W + (size_t)kr * HDIM + h0 + wcol) : f4z;
    };
    auto stsStage = [&]() {
        int rl = t >> 1;
#pragma unroll
        for (int j = 0; j < 4; j++) Xs[xkoff + j][rl] = (&xr0.x)[j];
#pragma unroll
        for (int j = 0; j < 4; j++) Xs[xkoff + 4 + j][rl] = (&xr1.x)[j];
        *(float4*)&Ws[wk][wcol] = wr;
    };

    loadStage(0);
    stsStage();
    __syncthreads();

    for (int s = 0; s < nStages; ++s) {
        if (s + 1 < nStages) loadStage((s + 1) * BK);
#pragma unroll
        for (int kk = 0; kk < BK; ++kk) {
            float4 b = *(const float4*)&Ws[kk][tx * 4];
            float4 a0 = *(const float4*)&Xs[kk][ty * 8];
            float4 a1 = *(const float4*)&Xs[kk][ty * 8 + 4];
            float av[8] = {a0.x, a0.y, a0.z, a0.w, a1.x, a1.y, a1.z, a1.w};
#pragma unroll
            for (int i = 0; i < 8; i++) {
                acc[i][0] = fmaf(av[i], b.x, acc[i][0]);
                acc[i][1] = fmaf(av[i], b.y, acc[i][1]);
                acc[i][2] = fmaf(av[i], b.z, acc[i][2]);
                acc[i][3] = fmaf(av[i], b.w, acc[i][3]);
            }
        }
        __syncthreads();
        if (s + 1 < nStages) { stsStage(); __syncthreads(); }
    }

    if (!wcolOk) return;
    float4 bb = f4z;
    if (EPI >= 1) bb = *(const float4*)&bias[h0 + wcol];
#pragma unroll
    for (int i = 0; i < 8; i++) {
        size_t r = (size_t)(row0 + ty * 8 + i);
        float4 v;
        v.x = acc[i][0] + bb.x; v.y = acc[i][1] + bb.y;
        v.z = acc[i][2] + bb.z; v.w = acc[i][3] + bb.w;
        if (EPI == 1) { v.x = sspf(v.x); v.y = sspf(v.y); v.z = sspf(v.z); v.w = sspf(v.w); }
        if (EPI == 2) {
            float4 rv = *(const float4*)&res[r * HDIM + h0 + wcol];
            v.x += rv.x; v.y += rv.y; v.z += rv.z; v.w += rv.w;
        }
        *(float4*)&out[r * HDIM + h0 + wcol] = v;
    }
}

// ---------------- fused edge GEMM + aggregate ----------------
// block = 2 nodes (128 edges) x 64 h-cols:
// Wf = A@W2 + b2 ; msg[n,h] = sum_k C[e] * x1[nbr[e],h] * Wf[e,h]
__global__ __launch_bounds__(256) void edge_agg_kernel(
    const float* __restrict__ A, const float* __restrict__ W2,
    const float* __restrict__ b2, const float* __restrict__ x1,
    const int* __restrict__ nbr, const float* __restrict__ C,
    float* __restrict__ msg)
{
    __shared__ float Xs[BK][BM + 4];
    __shared__ float Ws[BK][BN + 4];
    __shared__ float red[16][BN + 4];
    const int t = threadIdx.x;
    const int ty = t >> 4, tx = t & 15;
    const int erow0 = blockIdx.x * BM;          // first edge of the pair
    const int h0 = blockIdx.y * BN;

    float acc[8][4];
#pragma unroll
    for (int i = 0; i < 8; i++)
#pragma unroll
        for (int j = 0; j < 4; j++) acc[i][j] = 0.f;

    const int nStages = (HDIM + BK - 1) / BK;   // 38
    const int xkoff = (t & 1) * 8;
    const float* Xrow = A + (size_t)(erow0 + (t >> 1)) * HDIM;
    const int wk = ty;
    const int wcol = tx * 4;
    const bool wcolOk = (h0 + wcol) < HDIM;

    float4 xr0, xr1, wr;
    const float4 f4z = make_float4(0.f, 0.f, 0.f, 0.f);

    auto loadStage = [&](int k0) {
        int kc = k0 + xkoff;
        xr0 = (kc < HDIM) ? *(const float4*)(Xrow + kc) : f4z;
        xr1 = (kc + 4 < HDIM) ? *(const float4*)(Xrow + kc + 4) : f4z;
        int kr = k0 + wk;
        wr = (kr < HDIM && wcolOk) ? *(const float4*)(W2 + (size_t)kr * HDIM + h0 + wcol) : f4z;
    };
    auto stsStage = [&]() {
        int rl = t >> 1;
#pragma unroll
        for (int j = 0; j < 4; j++) Xs[xkoff + j][rl] = (&xr0.x)[j];
#pragma unroll
        for (int j = 0; j < 4; j++) Xs[xkoff + 4 + j][rl] = (&xr1.x)[j];
        *(float4*)&Ws[wk][wcol] = wr;
    };

    loadStage(0);
    stsStage();
    __syncthreads();

    for (int s = 0; s < nStages; ++s) {
        if (s + 1 < nStages) loadStage((s + 1) * BK);
#pragma unroll
        for (int kk = 0; kk < BK; ++kk) {
            float4 b = *(const float4*)&Ws[kk][tx * 4];
            float4 a0 = *(const float4*)&Xs[kk][ty * 8];
            float4 a1 = *(const float4*)&Xs[kk][ty * 8 + 4];
            float av[8] = {a0.x, a0.y, a0.z, a0.w, a1.x, a1.y, a1.z, a1.w};
#pragma unroll
            for (int i = 0; i < 8; i++) {
                acc[i][0] = fmaf(av[i], b.x, acc[i][0]);
                acc[i][1] = fmaf(av[i], b.y, acc[i][1]);
                acc[i][2] = fmaf(av[i], b.z, acc[i][2]);
                acc[i][3] = fmaf(av[i], b.w, acc[i][3]);
            }
        }
        __syncthreads();
        if (s + 1 < nStages) { stsStage(); __syncthreads(); }
    }

    // epilogue: +b2, *C, *x1[nbr], reduce over edges-within-node
    float part[4] = {0.f, 0.f, 0.f, 0.f};
    float4 bb = wcolOk ? *(const float4*)&b2[h0 + wcol] : f4z;
    if (wcolOk) {
#pragma unroll
        for (int i = 0; i < 8; i++) {
            int e = erow0 + ty * 8 + i;
            float ce = C[e];
            if (ce != 0.f) {
                int nb = nbr[e];
                float4 xv = *(const float4*)&x1[(size_t)nb * HDIM + h0 + wcol];
                part[0] = fmaf((acc[i][0] + bb.x) * ce, xv.x, part[0]);
                part[1] = fmaf((acc[i][1] + bb.y) * ce, xv.y, part[1]);
                part[2] = fmaf((acc[i][2] + bb.z) * ce, xv.z, part[2]);
                part[3] = fmaf((acc[i][3] + bb.w) * ce, xv.w, part[3]);
            }
        }
    }
    *(float4*)&red[ty][wcol] = make_float4(part[0], part[1], part[2], part[3]);
    __syncthreads();
    if (t < 128) {
        int half = t >> 6;          // 0/1 -> node within pair (ty 0..7 / 8..15)
        int col = t & 63;
        if (h0 + col < HDIM) {
            float s = 0.f;
#pragma unroll
            for (int i = 0; i < 8; i++) s += red[half * 8 + i][col];
            msg[(size_t)(blockIdx.x * 2 + half) * HDIM + h0 + col] = s;
        }
    }
}

// ---------------- mean pool per graph ----------------
__global__ void pool_kernel(const float* __restrict__ h, float* __restrict__ pooled) {
    int b = blockIdx.x;
    int c = threadIdx.x;
    if (c >= HDIM) return;
    float s = 0.f;
    for (int n = 0; n < NPGC; n++) s += h[(size_t)(b * NPGC + n) * HDIM + c];
    pooled[b * HDIM + c] = s * (1.0f / 128.0f);
}

// ---------------- final linear: out = pooled @ pool_w + pool_b ----------------
__global__ void out_kernel(const float* __restrict__ pooled,
                           const float* __restrict__ pw,
                           const float* __restrict__ pb,
                           float* __restrict__ out) {
    __shared__ float prow[HDIM];
    int b = blockIdx.x;
    for (int i = threadIdx.x; i < HDIM; i += blockDim.x)
        prow[i] = pooled[b * HDIM + i];
    __syncthreads();
    int c = blockIdx.y * 128 + threadIdx.x;
    if (c < HDIM) {
        float s = pb[c];
        for (int k = 0; k < HDIM; k++)
            s = fmaf(prow[k], pw[k * HDIM + c], s);
        out[b * HDIM + c] = s;
    }
}

// ---------------- host launcher ----------------
extern "C" void kernel_launch(void* const* d_in, const int* in_sizes, int n_in,
                              void* d_out, int out_size) {
    // input-order detection: dict order starts with z (1024 ints); signature order with pos
    int zi, pi, base;
    if (in_sizes[0] == NNODES) { zi = 0; pi = 1; base = 2; }
    else                       { pi = 0; base = 1; zi = n_in - 1; }

    const int*   z   = (const int*)d_in[zi];
    const float* pos = (const float*)d_in[pi];
    const float* emb = (const float*)d_in[base + 0];
    const float* w1  = (const float*)d_in[base + 1];
    const float* b1  = (const float*)d_in[base + 2];
    const float* w2  = (const float*)d_in[base + 3];
    const float* b2  = (const float*)d_in[base + 4];
    const float* l1w = (const float*)d_in[base + 5];
    const float* l2w = (const float*)d_in[base + 6];
    const float* l2b = (const float*)d_in[base + 7];
    const float* ilw = (const float*)d_in[base + 8];
    const float* ilb = (const float*)d_in[base + 9];
    const float* pw  = (const float*)d_in[base + 10];
    const float* pb  = (const float*)d_in[base + 11];
    float* out = (float*)d_out;

    void* p;
    float *A, *ea, *hbase, *x1, *msgb, *tb, *pooled, *Cb, *db; int* nbrp;
    cudaGetSymbolAddress(&p, g_A);      A = (float*)p;
    cudaGetSymbolAddress(&p, g_eattr);  ea = (float*)p;
    cudaGetSymbolAddress(&p, g_h);      hbase = (float*)p;
    cudaGetSymbolAddress(&p, g_x1);     x1 = (float*)p;
    cudaGetSymbolAddress(&p, g_msg);    msgb = (float*)p;
    cudaGetSymbolAddress(&p, g_t);      tb = (float*)p;
    cudaGetSymbolAddress(&p, g_nbr);    nbrp = (int*)p;
    cudaGetSymbolAddress(&p, g_C);      Cb = (float*)p;
    cudaGetSymbolAddress(&p, g_d);      db = (float*)p;
    cudaGetSymbolAddress(&p, g_pooled); pooled = (float*)p;

    float* h0 = hbase;
    float* h1 = hbase + (size_t)NNODES * HDIM;

    build_graph_kernel<<<128, 256>>>(pos, nbrp, db, Cb);
    edge_feat_kernel<<<(NEDGE * EA_LD + 255) / 256, 256>>>(db, ea);
    embed_kernel<<<(NNODES * HDIM + 255) / 256, 256>>>(emb, z, h0);

    float* hc = h0;
    float* hn = h1;
    for (int l = 0; l < LAY; l++) {
        // x1 = h @ lin1_w (no bias)
        gemm_kernel<0><<<dim3(NNODES / BM, 10), 256>>>(
            hc, HDIM, HDIM, HDIM, l1w + (size_t)l * HDIM * HDIM, nullptr, nullptr, x1);
        // A = ssp(ea @ W1 + b1)
        gemm_kernel<1><<<dim3(NEDGE / BM, 10), 256>>>(
            ea, EA_LD, EA_LD, GDIM, w1 + (size_t)l * GDIM * HDIM, b1 + l * HDIM, nullptr, A);
        // msg = sum_k C * x1[nbr] * (A @ W2 + b2)
        edge_agg_kernel<<<dim3(NNODES / 2, 10), 256>>>(
            A, w2 + (size_t)l * HDIM * HDIM, b2 + l * HDIM, x1, nbrp, Cb, msgb);
        // t = ssp(msg @ lin2_w + lin2_b)
        gemm_kernel<1><<<dim3(NNODES / BM, 10), 256>>>(
            msgb, HDIM, HDIM, HDIM, l2w + (size_t)l * HDIM * HDIM, l2b + l * HDIM, nullptr, tb);
        // h_new = h + t @ int_lin_w + int_lin_b
        gemm_kernel<2><<<dim3(NNODES / BM, 10), 256>>>(
            tb, HDIM, HDIM, HDIM, ilw + (size_t)l * HDIM * HDIM, ilb + l * HDIM, hc, hn);
        float* tmp = hc; hc = hn; hn = tmp;
    }

    pool_kernel<<<NBG, 640>>>(hc, pooled);
    out_kernel<<<dim3(NBG, 5), 128>>>(pooled, pw, pb, out);
}